// round 2
// baseline (speedup 1.0000x reference)
#include <cuda_runtime.h>
#include <cuda_bf16.h>
#include <cfloat>
#include <cstdio>

#define BB   128
#define LQ   512
#define LK   512
#define DD   64
#define TQ   32      // q rows per block
#define TK   128     // k/v rows per tile
#define PPAD 516     // padded P row stride (floats)
#define KPAD 132     // padded transposed-K row stride (floats)
#define NTHREADS 256

// scratch for "attn-only" output layout case
__device__ float g_out_scratch[(size_t)BB * LQ * DD];

__global__ __launch_bounds__(NTHREADS, 2)
void sdpa_kernel(const float* __restrict__ q,
                 const float* __restrict__ k,
                 const float* __restrict__ v,
                 const int* __restrict__ km,
                 const int* __restrict__ qm,
                 float* __restrict__ out,
                 float* __restrict__ attn)
{
    extern __shared__ float smem[];
    float* P  = smem;                    // [TQ][PPAD]  scores -> probs
    float* KV = smem + TQ * PPAD;        // phase1: K^T [DD][KPAD]; phase2: V [TK][DD]
    float* Qs = KV + DD * KPAD;          // [TQ][DD]

    const int t  = threadIdx.x;
    const int b  = blockIdx.y;
    const int q0 = blockIdx.x * TQ;

    // ---- load Q tile (TQ*DD = 2048 floats = 512 float4) ----
    {
        const float4* qg = (const float4*)(q + ((size_t)b * LQ + q0) * DD);
        float4* qs4 = (float4*)Qs;
#pragma unroll
        for (int i = 0; i < 2; i++) qs4[t + NTHREADS * i] = qg[t + NTHREADS * i];
    }

    const int tx = t & 31;   // col group (4 contiguous k-cols)
    const int ty = t >> 5;   // q row group (4 rows)

    const float* kb = k + (size_t)b * LK * DD;

    // =================== Phase 1: S = Q K^T / 8 ===================
    for (int kt = 0; kt < LK / TK; kt++) {
        __syncthreads();
        // load K tile transposed: KV[d][krow], krow in [0,TK)
        {
            const float4* kg = (const float4*)(kb + (size_t)kt * TK * DD);
#pragma unroll
            for (int i = 0; i < 8; i++) {
                int idx = t + NTHREADS * i;     // float4 index in tile
                float4 val = kg[idx];
                int krow = idx >> 4;            // idx*4 / 64
                int d0   = (idx & 15) << 2;     // idx*4 % 64
                KV[(d0 + 0) * KPAD + krow] = val.x;
                KV[(d0 + 1) * KPAD + krow] = val.y;
                KV[(d0 + 2) * KPAD + krow] = val.z;
                KV[(d0 + 3) * KPAD + krow] = val.w;
            }
        }
        __syncthreads();

        float acc[4][4];
#pragma unroll
        for (int i = 0; i < 4; i++)
#pragma unroll
            for (int j = 0; j < 4; j++) acc[i][j] = 0.0f;

#pragma unroll
        for (int d4 = 0; d4 < DD; d4 += 4) {
            float4 kv0 = *(const float4*)&KV[(d4 + 0) * KPAD + (tx << 2)];
            float4 kv1 = *(const float4*)&KV[(d4 + 1) * KPAD + (tx << 2)];
            float4 kv2 = *(const float4*)&KV[(d4 + 2) * KPAD + (tx << 2)];
            float4 kv3 = *(const float4*)&KV[(d4 + 3) * KPAD + (tx << 2)];
#pragma unroll
            for (int i = 0; i < 4; i++) {
                float4 qv = *(const float4*)&Qs[((ty << 2) + i) * DD + d4];
                acc[i][0] = fmaf(qv.x, kv0.x, acc[i][0]);
                acc[i][0] = fmaf(qv.y, kv1.x, acc[i][0]);
                acc[i][0] = fmaf(qv.z, kv2.x, acc[i][0]);
                acc[i][0] = fmaf(qv.w, kv3.x, acc[i][0]);
                acc[i][1] = fmaf(qv.x, kv0.y, acc[i][1]);
                acc[i][1] = fmaf(qv.y, kv1.y, acc[i][1]);
                acc[i][1] = fmaf(qv.z, kv2.y, acc[i][1]);
                acc[i][1] = fmaf(qv.w, kv3.y, acc[i][1]);
                acc[i][2] = fmaf(qv.x, kv0.z, acc[i][2]);
                acc[i][2] = fmaf(qv.y, kv1.z, acc[i][2]);
                acc[i][2] = fmaf(qv.z, kv2.z, acc[i][2]);
                acc[i][2] = fmaf(qv.w, kv3.z, acc[i][2]);
                acc[i][3] = fmaf(qv.x, kv0.w, acc[i][3]);
                acc[i][3] = fmaf(qv.y, kv1.w, acc[i][3]);
                acc[i][3] = fmaf(qv.z, kv2.w, acc[i][3]);
                acc[i][3] = fmaf(qv.w, kv3.w, acc[i][3]);
            }
        }

        // store scaled scores into P
#pragma unroll
        for (int i = 0; i < 4; i++) {
            float4 s4;
            s4.x = acc[i][0] * 0.125f;
            s4.y = acc[i][1] * 0.125f;
            s4.z = acc[i][2] * 0.125f;
            s4.w = acc[i][3] * 0.125f;
            *(float4*)&P[((ty << 2) + i) * PPAD + kt * TK + (tx << 2)] = s4;
        }
    }
    __syncthreads();

    // =================== Softmax + masks (warp per row) ===================
    {
        const int warp = ty, lane = tx;
#pragma unroll
        for (int rr = 0; rr < 4; rr++) {
            const int r = warp + (rr << 3);
            float* Pr = P + r * PPAD;
            const size_t grow = ((size_t)b * LQ + q0 + r) * LK;
            const int4* kmr = (const int4*)(km + grow);
            const int4* qmr = (const int4*)(qm + grow);

            float vals[16];
            float mx = -FLT_MAX;
#pragma unroll
            for (int j = 0; j < 4; j++) {
                int c4 = lane + (j << 5);
                float4 s4 = *(const float4*)&Pr[c4 << 2];
                int4 m4 = kmr[c4];
                vals[j * 4 + 0] = m4.x ? -FLT_MAX : s4.x;
                vals[j * 4 + 1] = m4.y ? -FLT_MAX : s4.y;
                vals[j * 4 + 2] = m4.z ? -FLT_MAX : s4.z;
                vals[j * 4 + 3] = m4.w ? -FLT_MAX : s4.w;
                mx = fmaxf(mx, fmaxf(fmaxf(vals[j*4+0], vals[j*4+1]),
                                     fmaxf(vals[j*4+2], vals[j*4+3])));
            }
#pragma unroll
            for (int off = 16; off > 0; off >>= 1)
                mx = fmaxf(mx, __shfl_xor_sync(0xffffffffu, mx, off));

            float sum = 0.0f;
#pragma unroll
            for (int e = 0; e < 16; e++) {
                float ev = __expf(vals[e] - mx);   // masked: exp(-huge) == 0 exactly
                vals[e] = ev;
                sum += ev;
            }
#pragma unroll
            for (int off = 16; off > 0; off >>= 1)
                sum += __shfl_xor_sync(0xffffffffu, sum, off);

            const float inv = 1.0f / sum;

            float4* attn_row = attn ? (float4*)(attn + grow) : nullptr;
#pragma unroll
            for (int j = 0; j < 4; j++) {
                int c4 = lane + (j << 5);
                int4 m4 = qmr[c4];
                float4 a4;
                a4.x = m4.x ? 0.0f : vals[j * 4 + 0] * inv;
                a4.y = m4.y ? 0.0f : vals[j * 4 + 1] * inv;
                a4.z = m4.z ? 0.0f : vals[j * 4 + 2] * inv;
                a4.w = m4.w ? 0.0f : vals[j * 4 + 3] * inv;
                *(float4*)&Pr[c4 << 2] = a4;
                if (attn_row) attn_row[c4] = a4;
            }
        }
    }

    // =================== Phase 2: O = P V ===================
    const float* vb = v + (size_t)b * LK * DD;
    const int row2 = t >> 3;   // 0..31
    const int cg   = t & 7;    // 8 contiguous out cols
    float o0x=0,o0y=0,o0z=0,o0w=0,o1x=0,o1y=0,o1z=0,o1w=0;

    for (int kt2 = 0; kt2 < LK / TK; kt2++) {
        __syncthreads();
        {
            const float4* vg = (const float4*)(vb + (size_t)kt2 * TK * DD);
            float4* kv4 = (float4*)KV;
#pragma unroll
            for (int i = 0; i < 8; i++) kv4[t + NTHREADS * i] = vg[t + NTHREADS * i];
        }
        __syncthreads();

        const float* Pr2 = P + row2 * PPAD + kt2 * TK;
#pragma unroll 4
        for (int kk = 0; kk < TK; kk += 4) {
            float4 p4 = *(const float4*)&Pr2[kk];
            float pw[4] = {p4.x, p4.y, p4.z, p4.w};
#pragma unroll
            for (int u = 0; u < 4; u++) {
                const float4 va = *(const float4*)&KV[(kk + u) * DD + (cg << 3)];
                const float4 vb4 = *(const float4*)&KV[(kk + u) * DD + (cg << 3) + 4];
                o0x = fmaf(pw[u], va.x, o0x);
                o0y = fmaf(pw[u], va.y, o0y);
                o0z = fmaf(pw[u], va.z, o0z);
                o0w = fmaf(pw[u], va.w, o0w);
                o1x = fmaf(pw[u], vb4.x, o1x);
                o1y = fmaf(pw[u], vb4.y, o1y);
                o1z = fmaf(pw[u], vb4.z, o1z);
                o1w = fmaf(pw[u], vb4.w, o1w);
            }
        }
    }

    float* orow = out + ((size_t)b * LQ + q0 + row2) * DD + (cg << 3);
    *(float4*)orow       = make_float4(o0x, o0y, o0z, o0w);
    *(float4*)(orow + 4) = make_float4(o1x, o1y, o1z, o1w);
}

extern "C" void kernel_launch(void* const* d_in, const int* in_sizes, int n_in,
                              void* d_out, int out_size)
{
    const float* q = (const float*)d_in[0];
    const float* k = (const float*)d_in[1];
    const float* v = (const float*)d_in[2];
    const int* km = (const int*)d_in[3];
    const int* qm = (const int*)d_in[4];

    const long long OUT_N  = (long long)BB * LQ * DD;     //  4,194,304
    const long long ATTN_N = (long long)BB * LQ * LK;     // 33,554,432

    float* out_p;
    float* attn_p;
    long long osz = (long long)out_size;
    if (osz >= OUT_N + ATTN_N) {            // tuple (output, attn) concatenated
        out_p  = (float*)d_out;
        attn_p = (float*)d_out + OUT_N;
    } else if (osz == ATTN_N) {             // attn only
        float* scratch;
        cudaGetSymbolAddress((void**)&scratch, g_out_scratch);
        out_p  = scratch;
        attn_p = (float*)d_out;
    } else {                                // output only
        out_p  = (float*)d_out;
        attn_p = nullptr;
    }

    const int smem_bytes = (TQ * PPAD + DD * KPAD + TQ * DD) * (int)sizeof(float);
    cudaFuncSetAttribute(sdpa_kernel, cudaFuncAttributeMaxDynamicSharedMemorySize, smem_bytes);

    dim3 grid(LQ / TQ, BB);
    sdpa_kernel<<<grid, NTHREADS, smem_bytes>>>(q, k, v, km, qm, out_p, attn_p);
}

// round 3
// speedup vs baseline: 2.2147x; 2.2147x over previous
#include <cuda_runtime.h>
#include <cuda_bf16.h>
#include <cfloat>
#include <cstdio>

#define BB   128
#define LQ   512
#define LK   512
#define DD   64
#define TQ   32      // q rows per block
#define TK   128     // k/v rows per tile
#define PPAD 516     // padded P row stride (floats)
#define QTP  36      // padded Qt row stride (floats)
#define NTHREADS 256

// scratch for "attn-only" output layout case
__device__ float g_out_scratch[(size_t)BB * LQ * DD];

__global__ __launch_bounds__(NTHREADS, 2)
void sdpa_kernel(const float* __restrict__ q,
                 const float* __restrict__ k,
                 const float* __restrict__ v,
                 const int* __restrict__ km,
                 const int* __restrict__ qm,
                 float* __restrict__ out,
                 float* __restrict__ attn)
{
    extern __shared__ float smem[];
    float* P  = smem;                    // [TQ][PPAD]  scores -> probs
    float* KV = smem + TQ * PPAD;        // phase1: K (swizzled) [TK][64]; phase2: V [TK][64]
    float* Qt = KV + TK * DD;            // Q transposed [DD][QTP]

    const int t  = threadIdx.x;
    const int b  = blockIdx.y;
    const int q0 = blockIdx.x * TQ;

    const int tx = t & 31;   // col group (4 contiguous k-cols)
    const int ty = t >> 5;   // warp id = q row group (4 rows)

    // ---- load Q tile transposed: Qt[d][row] ----
    {
        const float4* qg = (const float4*)(q + ((size_t)b * LQ + q0) * DD);
#pragma unroll
        for (int i = 0; i < 2; i++) {
            int idx = t + NTHREADS * i;      // float4 index over 512
            float4 val = qg[idx];
            int qrow = idx >> 4;             // 0..31
            int d0   = (idx & 15) << 2;      // 0..60
            Qt[(d0 + 0) * QTP + qrow] = val.x;
            Qt[(d0 + 1) * QTP + qrow] = val.y;
            Qt[(d0 + 2) * QTP + qrow] = val.z;
            Qt[(d0 + 3) * QTP + qrow] = val.w;
        }
    }

    const float* kb = k + (size_t)b * LK * DD;
    const int swz = tx & 7;                 // xor-swizzle key for this thread's cols
    // word bases for this thread's 4 k-cols (c = 4*tx + j), row-major 64 floats/row
    const int cb0 = (4 * tx + 0) * DD;
    const int cb1 = (4 * tx + 1) * DD;
    const int cb2 = (4 * tx + 2) * DD;
    const int cb3 = (4 * tx + 3) * DD;

    // =================== Phase 1: S = Q K^T / 8 ===================
    for (int kt = 0; kt < LK / TK; kt++) {
        __syncthreads();
        // stage K tile row-major with XOR quad swizzle: element K[krow][d] at
        // word krow*64 + ((d>>2 ^ ((krow>>2)&7))<<2) + (d&3)
        {
            const float4* kg = (const float4*)(kb + (size_t)kt * TK * DD);
#pragma unroll
            for (int i = 0; i < 8; i++) {
                int idx = t + NTHREADS * i;     // float4 index in tile (2048)
                float4 val = kg[idx];
                int krow = idx >> 4;            // 0..127
                int qq   = idx & 15;            // d-quad 0..15
                int pw   = krow * DD + (((qq) ^ ((krow >> 2) & 7)) << 2);
                *(float4*)&KV[pw] = val;
            }
        }
        __syncthreads();

        float acc[4][4];
#pragma unroll
        for (int i = 0; i < 4; i++)
#pragma unroll
            for (int j = 0; j < 4; j++) acc[i][j] = 0.0f;

#pragma unroll
        for (int d4 = 0; d4 < DD; d4 += 4) {
            const int pq = (((d4 >> 2) ^ swz) << 2);
            float kq[4][4];   // [col][dd]
            *(float4*)kq[0] = *(const float4*)&KV[cb0 + pq];
            *(float4*)kq[1] = *(const float4*)&KV[cb1 + pq];
            *(float4*)kq[2] = *(const float4*)&KV[cb2 + pq];
            *(float4*)kq[3] = *(const float4*)&KV[cb3 + pq];
            float qqv[4][4];  // [dd][row] -- broadcast loads (same addr across warp)
#pragma unroll
            for (int dd = 0; dd < 4; dd++)
                *(float4*)qqv[dd] = *(const float4*)&Qt[(d4 + dd) * QTP + (ty << 2)];
#pragma unroll
            for (int dd = 0; dd < 4; dd++)
#pragma unroll
                for (int i = 0; i < 4; i++)
#pragma unroll
                    for (int j = 0; j < 4; j++)
                        acc[i][j] = fmaf(qqv[dd][i], kq[j][dd], acc[i][j]);
        }

        // store scaled scores into P
#pragma unroll
        for (int i = 0; i < 4; i++) {
            float4 s4;
            s4.x = acc[i][0] * 0.125f;
            s4.y = acc[i][1] * 0.125f;
            s4.z = acc[i][2] * 0.125f;
            s4.w = acc[i][3] * 0.125f;
            *(float4*)&P[((ty << 2) + i) * PPAD + kt * TK + (tx << 2)] = s4;
        }
    }
    __syncthreads();

    // =================== Softmax + masks (warp per row) ===================
    {
        const int warp = ty, lane = tx;
#pragma unroll
        for (int rr = 0; rr < 4; rr++) {
            const int r = warp + (rr << 3);
            float* Pr = P + r * PPAD;
            const size_t grow = ((size_t)b * LQ + q0 + r) * LK;
            const int4* kmr = (const int4*)(km + grow);
            const int4* qmr = (const int4*)(qm + grow);

            float vals[16];
            float mx = -FLT_MAX;
#pragma unroll
            for (int j = 0; j < 4; j++) {
                int c4 = lane + (j << 5);
                float4 s4 = *(const float4*)&Pr[c4 << 2];
                int4 m4 = kmr[c4];
                vals[j * 4 + 0] = m4.x ? -FLT_MAX : s4.x;
                vals[j * 4 + 1] = m4.y ? -FLT_MAX : s4.y;
                vals[j * 4 + 2] = m4.z ? -FLT_MAX : s4.z;
                vals[j * 4 + 3] = m4.w ? -FLT_MAX : s4.w;
                mx = fmaxf(mx, fmaxf(fmaxf(vals[j*4+0], vals[j*4+1]),
                                     fmaxf(vals[j*4+2], vals[j*4+3])));
            }
#pragma unroll
            for (int off = 16; off > 0; off >>= 1)
                mx = fmaxf(mx, __shfl_xor_sync(0xffffffffu, mx, off));

            float sum = 0.0f;
#pragma unroll
            for (int e = 0; e < 16; e++) {
                float ev = __expf(vals[e] - mx);   // masked: exp(-huge) == 0 exactly
                vals[e] = ev;
                sum += ev;
            }
#pragma unroll
            for (int off = 16; off > 0; off >>= 1)
                sum += __shfl_xor_sync(0xffffffffu, sum, off);

            const float inv = 1.0f / sum;

            float4* attn_row = attn ? (float4*)(attn + grow) : nullptr;
#pragma unroll
            for (int j = 0; j < 4; j++) {
                int c4 = lane + (j << 5);
                int4 m4 = qmr[c4];
                float4 a4;
                a4.x = m4.x ? 0.0f : vals[j * 4 + 0] * inv;
                a4.y = m4.y ? 0.0f : vals[j * 4 + 1] * inv;
                a4.z = m4.z ? 0.0f : vals[j * 4 + 2] * inv;
                a4.w = m4.w ? 0.0f : vals[j * 4 + 3] * inv;
                *(float4*)&Pr[c4 << 2] = a4;
                if (attn_row) attn_row[c4] = a4;
            }
        }
    }

    // =================== Phase 2: O = P V ===================
    // warp ty handles rows 4*ty..4*ty+3; lane tx owns cols 2*tx, 2*tx+1
    const float* vb = v + (size_t)b * LK * DD;
    const int r0 = ty << 2;
    const int c2 = tx << 1;
    float acc2[4][2];
#pragma unroll
    for (int r = 0; r < 4; r++) { acc2[r][0] = 0.0f; acc2[r][1] = 0.0f; }

    for (int kt2 = 0; kt2 < LK / TK; kt2++) {
        __syncthreads();
        {
            const float4* vg = (const float4*)(vb + (size_t)kt2 * TK * DD);
            float4* kv4 = (float4*)KV;
#pragma unroll
            for (int i = 0; i < 8; i++) kv4[t + NTHREADS * i] = vg[t + NTHREADS * i];
        }
        __syncthreads();

#pragma unroll 4
        for (int kk = 0; kk < TK; kk += 4) {
            float pr[4][4];   // [row][u] -- broadcast loads
#pragma unroll
            for (int r = 0; r < 4; r++)
                *(float4*)pr[r] = *(const float4*)&P[(r0 + r) * PPAD + kt2 * TK + kk];
#pragma unroll
            for (int u = 0; u < 4; u++) {
                float2 v2 = *(const float2*)&KV[(kk + u) * DD + c2];
#pragma unroll
                for (int r = 0; r < 4; r++) {
                    acc2[r][0] = fmaf(pr[r][u], v2.x, acc2[r][0]);
                    acc2[r][1] = fmaf(pr[r][u], v2.y, acc2[r][1]);
                }
            }
        }
    }

#pragma unroll
    for (int r = 0; r < 4; r++) {
        float* orow = out + ((size_t)b * LQ + q0 + r0 + r) * DD + c2;
        *(float2*)orow = make_float2(acc2[r][0], acc2[r][1]);
    }
}

extern "C" void kernel_launch(void* const* d_in, const int* in_sizes, int n_in,
                              void* d_out, int out_size)
{
    const float* q = (const float*)d_in[0];
    const float* k = (const float*)d_in[1];
    const float* v = (const float*)d_in[2];
    const int* km = (const int*)d_in[3];
    const int* qm = (const int*)d_in[4];

    const long long OUT_N  = (long long)BB * LQ * DD;     //  4,194,304
    const long long ATTN_N = (long long)BB * LQ * LK;     // 33,554,432

    float* out_p;
    float* attn_p;
    long long osz = (long long)out_size;
    if (osz >= OUT_N + ATTN_N) {            // tuple (output, attn) concatenated
        out_p  = (float*)d_out;
        attn_p = (float*)d_out + OUT_N;
    } else if (osz == ATTN_N) {             // attn only
        float* scratch;
        cudaGetSymbolAddress((void**)&scratch, g_out_scratch);
        out_p  = scratch;
        attn_p = (float*)d_out;
    } else {                                // output only
        out_p  = (float*)d_out;
        attn_p = nullptr;
    }

    const int smem_bytes = (TQ * PPAD + TK * DD + DD * QTP) * (int)sizeof(float);
    cudaFuncSetAttribute(sdpa_kernel, cudaFuncAttributeMaxDynamicSharedMemorySize, smem_bytes);

    dim3 grid(LQ / TQ, BB);
    sdpa_kernel<<<grid, NTHREADS, smem_bytes>>>(q, k, v, km, qm, out_p, attn_p);
}

// round 5
// speedup vs baseline: 3.6455x; 1.6460x over previous
#include <cuda_runtime.h>
#include <cuda_fp16.h>
#include <cfloat>
#include <cstdint>

#define BB 128
#define LQ 512
#define LK 512
#define DD 64
#define TQ 32
#define TK 128
#define NCH (LK/TK)          // 4
#define PPAD 516             // fp32 P stride (floats)
#define PHS  520             // fp16 attn stride (halves) -> 1040 B/row
#define KS   72              // K/V fp16 row stride (halves) -> 144 B/row
#define QSP  68              // Q fp32 stride
#define NTHREADS 256

// smem byte offsets
#define OFF_P   0
#define OFF_PH  66048                      // 32*516*4
#define OFF_K0  (OFF_PH + 33280)           // 32*520*2
#define OFF_K1  (OFF_K0 + 36864)           // hi(18432)+lo(18432)
#define OFF_QS  (OFF_K1 + 36864)
#define SMEM_BYTES (OFF_QS + 8704)         // 32*68*4 -> 181760
#define KHALF 18432                        // bytes per (hi|lo) half of a K buffer
#define OFF_V0  OFF_K0                     // V tiles alias K buffers (phase 2)
#define OFF_V1  (OFF_K0 + KHALF)

__device__ float g_out_scratch[(size_t)BB * LQ * DD];

static __device__ __forceinline__ uint32_t s2u(const void* p) {
    uint32_t a;
    asm("{ .reg .u64 t; cvta.to.shared.u64 t, %1; cvt.u32.u64 %0, t; }" : "=r"(a) : "l"(p));
    return a;
}
static __device__ __forceinline__ uint32_t pack_hi(float x, float y) {
    __half2 h = __floats2half2_rn(x, y);
    return *(uint32_t*)&h;
}
static __device__ __forceinline__ uint32_t pack_lo(float x, float y, uint32_t hibits) {
    __half2 h = *(__half2*)&hibits;
    float2 hf = __half22float2(h);
    __half2 l = __floats2half2_rn(x - hf.x, y - hf.y);
    return *(uint32_t*)&l;
}
static __device__ __forceinline__ void mma16816(float& c0, float& c1, float& c2, float& c3,
                                                uint32_t a0, uint32_t a1, uint32_t a2, uint32_t a3,
                                                uint32_t b0, uint32_t b1) {
    asm volatile("mma.sync.aligned.m16n8k16.row.col.f32.f16.f16.f32 "
                 "{%0,%1,%2,%3}, {%4,%5,%6,%7}, {%8,%9}, {%0,%1,%2,%3};"
                 : "+f"(c0), "+f"(c1), "+f"(c2), "+f"(c3)
                 : "r"(a0), "r"(a1), "r"(a2), "r"(a3), "r"(b0), "r"(b1));
}
static __device__ __forceinline__ void ldsm4(uint32_t& r0, uint32_t& r1, uint32_t& r2, uint32_t& r3,
                                             uint32_t addr) {
    asm volatile("ldmatrix.sync.aligned.m8n8.x4.shared.b16 {%0,%1,%2,%3}, [%4];"
                 : "=r"(r0), "=r"(r1), "=r"(r2), "=r"(r3) : "r"(addr));
}
static __device__ __forceinline__ void ldsm4t(uint32_t& r0, uint32_t& r1, uint32_t& r2, uint32_t& r3,
                                              uint32_t addr) {
    asm volatile("ldmatrix.sync.aligned.m8n8.x4.trans.shared.b16 {%0,%1,%2,%3}, [%4];"
                 : "=r"(r0), "=r"(r1), "=r"(r2), "=r"(r3) : "r"(addr));
}

__global__ __launch_bounds__(NTHREADS, 1)
void sdpa_mma_kernel(const float* __restrict__ q,
                     const float* __restrict__ k,
                     const float* __restrict__ v,
                     const int* __restrict__ km,
                     const int* __restrict__ qm,
                     float* __restrict__ out,
                     float* __restrict__ attn)
{
    extern __shared__ char sm[];
    const uint32_t sbase = s2u(sm);
    float* P  = (float*)(sm + OFF_P);
    float* Qs = (float*)(sm + OFF_QS);

    const int t = threadIdx.x;
    const int w = t >> 5, l = t & 31;
    const int g = l >> 2, tq = l & 3;
    const int b = blockIdx.y;
    const int q0 = blockIdx.x * TQ;

    const float* kb = k + (size_t)b * LK * DD;
    const float* vb = v + (size_t)b * LK * DD;

    // ---- stage Q (fp32, coalesced) + K tile 0 (hi/lo fp16) ----
    {
        const float4* qg = (const float4*)(q + ((size_t)b * LQ + q0) * DD);
#pragma unroll
        for (int i = 0; i < 2; i++) {
            int idx = t + NTHREADS * i;         // 0..511
            float4 val = qg[idx];
            *(float4*)&Qs[(idx >> 4) * QSP + ((idx & 15) << 2)] = val;
        }
        const float4* kg = (const float4*)kb;
#pragma unroll
        for (int i = 0; i < 8; i++) {
            int idx = t + NTHREADS * i;         // 0..2047
            float4 val = kg[idx];
            int krow = idx >> 4, d0 = (idx & 15) << 2;
            uint2 hi, lo;
            hi.x = pack_hi(val.x, val.y); hi.y = pack_hi(val.z, val.w);
            lo.x = pack_lo(val.x, val.y, hi.x); lo.y = pack_lo(val.z, val.w, hi.y);
            *(uint2*)(sm + OFF_K0 + (krow * KS + d0) * 2) = hi;
            *(uint2*)(sm + OFF_K0 + KHALF + (krow * KS + d0) * 2) = lo;
        }
    }
    __syncthreads();

    // ---- build Q fragments (hi/lo fp16), held in registers ----
    const int rg = w & 1;          // phase-1 row group
    const int cg1 = w >> 1;        // phase-1 col group (32 cols)
    const int r0i = rg * 16 + g, r1i = r0i + 8;
    uint32_t ahh[4][4], alo[4][4];
#pragma unroll
    for (int s = 0; s < 4; s++) {
        int k0 = 16 * s + 2 * tq;
        float2 p00 = *(float2*)&Qs[r0i * QSP + k0];
        float2 p01 = *(float2*)&Qs[r0i * QSP + k0 + 8];
        float2 p10 = *(float2*)&Qs[r1i * QSP + k0];
        float2 p11 = *(float2*)&Qs[r1i * QSP + k0 + 8];
        ahh[s][0] = pack_hi(p00.x, p00.y); alo[s][0] = pack_lo(p00.x, p00.y, ahh[s][0]);
        ahh[s][1] = pack_hi(p10.x, p10.y); alo[s][1] = pack_lo(p10.x, p10.y, ahh[s][1]);
        ahh[s][2] = pack_hi(p01.x, p01.y); alo[s][2] = pack_lo(p01.x, p01.y, ahh[s][2]);
        ahh[s][3] = pack_hi(p11.x, p11.y); alo[s][3] = pack_lo(p11.x, p11.y, ahh[s][3]);
    }

    // =================== Phase 1: S = Q K^T (fp16 x3) ===================
    for (int kt = 0; kt < NCH; kt++) {
        float4 pre[8];
        if (kt + 1 < NCH) {
            const float4* kg = (const float4*)(kb + (size_t)(kt + 1) * TK * DD);
#pragma unroll
            for (int i = 0; i < 8; i++) pre[i] = kg[t + NTHREADS * i];
        }
        const char* kbuf = sm + ((kt & 1) ? OFF_K1 : OFF_K0);

        float acc[4][4];
#pragma unroll
        for (int nt = 0; nt < 4; nt++)
#pragma unroll
            for (int j = 0; j < 4; j++) acc[nt][j] = 0.0f;

#pragma unroll
        for (int s = 0; s < 4; s++) {
#pragma unroll
            for (int nt = 0; nt < 4; nt++) {
                int row = cg1 * 32 + nt * 8 + g;
                int byte = (row * KS + 16 * s + 2 * tq) * 2;
                uint32_t bh0 = *(const uint32_t*)(kbuf + byte);
                uint32_t bh1 = *(const uint32_t*)(kbuf + byte + 16);
                uint32_t bl0 = *(const uint32_t*)(kbuf + KHALF + byte);
                uint32_t bl1 = *(const uint32_t*)(kbuf + KHALF + byte + 16);
                mma16816(acc[nt][0], acc[nt][1], acc[nt][2], acc[nt][3],
                         ahh[s][0], ahh[s][1], ahh[s][2], ahh[s][3], bh0, bh1);
                mma16816(acc[nt][0], acc[nt][1], acc[nt][2], acc[nt][3],
                         ahh[s][0], ahh[s][1], ahh[s][2], ahh[s][3], bl0, bl1);
                mma16816(acc[nt][0], acc[nt][1], acc[nt][2], acc[nt][3],
                         alo[s][0], alo[s][1], alo[s][2], alo[s][3], bh0, bh1);
            }
        }
        // write scaled scores to P (fp32)
#pragma unroll
        for (int nt = 0; nt < 4; nt++) {
            int cb = kt * TK + cg1 * 32 + nt * 8 + 2 * tq;
            *(float2*)&P[r0i * PPAD + cb] = make_float2(acc[nt][0] * 0.125f, acc[nt][1] * 0.125f);
            *(float2*)&P[r1i * PPAD + cb] = make_float2(acc[nt][2] * 0.125f, acc[nt][3] * 0.125f);
        }
        if (kt + 1 < NCH) {
            char* nbuf = sm + (((kt + 1) & 1) ? OFF_K1 : OFF_K0);
#pragma unroll
            for (int i = 0; i < 8; i++) {
                int idx = t + NTHREADS * i;
                int krow = idx >> 4, d0 = (idx & 15) << 2;
                uint2 hi, lo;
                hi.x = pack_hi(pre[i].x, pre[i].y); hi.y = pack_hi(pre[i].z, pre[i].w);
                lo.x = pack_lo(pre[i].x, pre[i].y, hi.x); lo.y = pack_lo(pre[i].z, pre[i].w, hi.y);
                *(uint2*)(nbuf + (krow * KS + d0) * 2) = hi;
                *(uint2*)(nbuf + KHALF + (krow * KS + d0) * 2) = lo;
            }
        }
        __syncthreads();
    }

    // =================== Softmax + masks (warp per row) ===================
    {
#pragma unroll
        for (int rr = 0; rr < 4; rr++) {
            const int r = w + (rr << 3);
            float* Pr = P + r * PPAD;
            const size_t grow = ((size_t)(b * LQ) + q0 + r) * LK;
            const int4* kmr = (const int4*)(km + grow);
            const int4* qmr = (const int4*)(qm + grow);

            float vals[16];
            float mx = -FLT_MAX;
#pragma unroll
            for (int j = 0; j < 4; j++) {
                int c4 = l + (j << 5);
                float4 s4 = *(const float4*)&Pr[c4 << 2];
                int4 m4 = kmr[c4];
                vals[j * 4 + 0] = m4.x ? -FLT_MAX : s4.x;
                vals[j * 4 + 1] = m4.y ? -FLT_MAX : s4.y;
                vals[j * 4 + 2] = m4.z ? -FLT_MAX : s4.z;
                vals[j * 4 + 3] = m4.w ? -FLT_MAX : s4.w;
                mx = fmaxf(mx, fmaxf(fmaxf(vals[j*4+0], vals[j*4+1]),
                                     fmaxf(vals[j*4+2], vals[j*4+3])));
            }
#pragma unroll
            for (int off = 16; off > 0; off >>= 1)
                mx = fmaxf(mx, __shfl_xor_sync(0xffffffffu, mx, off));

            float sum = 0.0f;
#pragma unroll
            for (int e = 0; e < 16; e++) {
                float ev = __expf(vals[e] - mx);
                vals[e] = ev;
                sum += ev;
            }
#pragma unroll
            for (int off = 16; off > 0; off >>= 1)
                sum += __shfl_xor_sync(0xffffffffu, sum, off);

            const float inv = 1.0f / sum;
            float4* attn_row = attn ? (float4*)(attn + grow) : nullptr;
#pragma unroll
            for (int j = 0; j < 4; j++) {
                int c4 = l + (j << 5);
                int4 m4 = qmr[c4];
                float4 a4;
                a4.x = m4.x ? 0.0f : vals[j * 4 + 0] * inv;
                a4.y = m4.y ? 0.0f : vals[j * 4 + 1] * inv;
                a4.z = m4.z ? 0.0f : vals[j * 4 + 2] * inv;
                a4.w = m4.w ? 0.0f : vals[j * 4 + 3] * inv;
                // fp16 copy for the O-GEMM
                uint2 ph;
                ph.x = pack_hi(a4.x, a4.y);
                ph.y = pack_hi(a4.z, a4.w);
                *(uint2*)(sm + OFF_PH + r * (PHS * 2) + c4 * 8) = ph;
                if (attn_row) attn_row[c4] = a4;
            }
        }
    }

    // stage V tile 0 (fp16) — K buffers are free now
    {
        const float4* vg = (const float4*)vb;
#pragma unroll
        for (int i = 0; i < 8; i++) {
            int idx = t + NTHREADS * i;
            float4 val = vg[idx];
            int krow = idx >> 4, d0 = (idx & 15) << 2;
            uint2 h;
            h.x = pack_hi(val.x, val.y); h.y = pack_hi(val.z, val.w);
            *(uint2*)(sm + OFF_V0 + (krow * KS + d0) * 2) = h;
        }
    }
    __syncthreads();

    // =================== Phase 2: O = attn * V (fp16) ===================
    const int rg2 = w & 1;
    const int cg2 = w >> 1;          // 16 out cols each
    float o[2][4];
#pragma unroll
    for (int nt = 0; nt < 2; nt++)
#pragma unroll
        for (int j = 0; j < 4; j++) o[nt][j] = 0.0f;

    const uint32_t a_base = sbase + OFF_PH + (rg2 * 16 + (l & 15)) * (PHS * 2) + ((l >> 4) & 1) * 16;
    const uint32_t b_coloff = (cg2 * 16 + ((l >> 4) & 1) * 8) * 2;

    for (int vt = 0; vt < NCH; vt++) {
        float4 pre[8];
        if (vt + 1 < NCH) {
            const float4* vg = (const float4*)(vb + (size_t)(vt + 1) * TK * DD);
#pragma unroll
            for (int i = 0; i < 8; i++) pre[i] = vg[t + NTHREADS * i];
        }
        const uint32_t vbuf = sbase + ((vt & 1) ? OFF_V1 : OFF_V0);
#pragma unroll
        for (int s = 0; s < 8; s++) {
            uint32_t a0, a1, a2, a3, b0, b1, b2, b3;
            ldsm4(a0, a1, a2, a3, a_base + (vt * TK + s * 16) * 2);
            ldsm4t(b0, b1, b2, b3, vbuf + (s * 16 + (l & 15)) * (KS * 2) + b_coloff);
            mma16816(o[0][0], o[0][1], o[0][2], o[0][3], a0, a1, a2, a3, b0, b1);
            mma16816(o[1][0], o[1][1], o[1][2], o[1][3], a0, a1, a2, a3, b2, b3);
        }
        if (vt + 1 < NCH) {
            char* nbuf = sm + (((vt + 1) & 1) ? OFF_V1 : OFF_V0);
#pragma unroll
            for (int i = 0; i < 8; i++) {
                int idx = t + NTHREADS * i;
                int krow = idx >> 4, d0 = (idx & 15) << 2;
                uint2 h;
                h.x = pack_hi(pre[i].x, pre[i].y); h.y = pack_hi(pre[i].z, pre[i].w);
                *(uint2*)(nbuf + (krow * KS + d0) * 2) = h;
            }
        }
        __syncthreads();
    }

    // write O
    {
        const int row0 = q0 + rg2 * 16 + g;
#pragma unroll
        for (int nt = 0; nt < 2; nt++) {
            int col = cg2 * 16 + nt * 8 + 2 * tq;
            *(float2*)(out + ((size_t)(b * LQ) + row0) * DD + col) = make_float2(o[nt][0], o[nt][1]);
            *(float2*)(out + ((size_t)(b * LQ) + row0 + 8) * DD + col) = make_float2(o[nt][2], o[nt][3]);
        }
    }
}

extern "C" void kernel_launch(void* const* d_in, const int* in_sizes, int n_in,
                              void* d_out, int out_size)
{
    const float* q = (const float*)d_in[0];
    const float* k = (const float*)d_in[1];
    const float* v = (const float*)d_in[2];
    const int* km = (const int*)d_in[3];
    const int* qm = (const int*)d_in[4];

    const long long OUT_N  = (long long)BB * LQ * DD;
    const long long ATTN_N = (long long)BB * LQ * LK;

    float* out_p;
    float* attn_p;
    long long osz = (long long)out_size;
    if (osz >= OUT_N + ATTN_N) {
        out_p  = (float*)d_out;
        attn_p = (float*)d_out + OUT_N;
    } else if (osz == ATTN_N) {
        float* scratch;
        cudaGetSymbolAddress((void**)&scratch, g_out_scratch);
        out_p  = scratch;
        attn_p = (float*)d_out;
    } else {
        out_p  = (float*)d_out;
        attn_p = nullptr;
    }

    cudaFuncSetAttribute(sdpa_mma_kernel, cudaFuncAttributeMaxDynamicSharedMemorySize, SMEM_BYTES);
    dim3 grid(LQ / TQ, BB);
    sdpa_mma_kernel<<<grid, NTHREADS, SMEM_BYTES>>>(q, k, v, km, qm, out_p, attn_p);
}

// round 11
// speedup vs baseline: 4.0998x; 1.1246x over previous
#include <cuda_runtime.h>
#include <cuda_fp16.h>
#include <cfloat>
#include <cstdint>

#define BB 128
#define LQ 512
#define LK 512
#define DD 64
#define TQ 32
#define TK 64
#define NCH (LK/TK)          // 8
#define PHS  520             // fp16 E stride (halves) -> 1040 B/row
#define KS   72              // K/V fp16 row stride (halves) -> 144 B/row
#define QSP  68              // Q fp32 stride
#define NTHREADS 256

// smem byte offsets
#define OFF_PH 0                           // 32*520*2 = 33280
#define OFF_K0 33280                       // hi(9216)+lo(9216)
#define KHALF  9216
#define OFF_K1 (OFF_K0 + 2*KHALF)          // 51712
#define OFF_QS (OFF_K1 + 2*KHALF)          // 70144, 32*68*4 = 8704
#define OFF_Z  (OFF_QS + 8704)             // 78848, 128 B
#define SMEM_BYTES (OFF_Z + 128)           // 78976
#define OFF_V0 OFF_K0                      // V buffers alias K region (fp16 only)
#define OFF_V1 (OFF_K0 + KHALF)

__device__ float g_out_scratch[(size_t)BB * LQ * DD];

static __device__ __forceinline__ uint32_t s2u(const void* p) {
    uint32_t a;
    asm("{ .reg .u64 t; cvta.to.shared.u64 t, %1; cvt.u32.u64 %0, t; }" : "=r"(a) : "l"(p));
    return a;
}
static __device__ __forceinline__ uint32_t pack_hi(float x, float y) {
    __half2 h = __floats2half2_rn(x, y);
    return *(uint32_t*)&h;
}
static __device__ __forceinline__ uint32_t pack_lo(float x, float y, uint32_t hibits) {
    __half2 h = *(__half2*)&hibits;
    float2 hf = __half22float2(h);
    __half2 l = __floats2half2_rn(x - hf.x, y - hf.y);
    return *(uint32_t*)&l;
}
static __device__ __forceinline__ void mma16816(float& c0, float& c1, float& c2, float& c3,
                                                uint32_t a0, uint32_t a1, uint32_t a2, uint32_t a3,
                                                uint32_t b0, uint32_t b1) {
    asm volatile("mma.sync.aligned.m16n8k16.row.col.f32.f16.f16.f32 "
                 "{%0,%1,%2,%3}, {%4,%5,%6,%7}, {%8,%9}, {%0,%1,%2,%3};"
                 : "+f"(c0), "+f"(c1), "+f"(c2), "+f"(c3)
                 : "r"(a0), "r"(a1), "r"(a2), "r"(a3), "r"(b0), "r"(b1));
}
static __device__ __forceinline__ void ldsm4(uint32_t& r0, uint32_t& r1, uint32_t& r2, uint32_t& r3,
                                             uint32_t addr) {
    asm volatile("ldmatrix.sync.aligned.m8n8.x4.shared.b16 {%0,%1,%2,%3}, [%4];"
                 : "=r"(r0), "=r"(r1), "=r"(r2), "=r"(r3) : "r"(addr));
}
static __device__ __forceinline__ void ldsm4t(uint32_t& r0, uint32_t& r1, uint32_t& r2, uint32_t& r3,
                                              uint32_t addr) {
    asm volatile("ldmatrix.sync.aligned.m8n8.x4.trans.shared.b16 {%0,%1,%2,%3}, [%4];"
                 : "=r"(r0), "=r"(r1), "=r"(r2), "=r"(r3) : "r"(addr));
}

__global__ __launch_bounds__(NTHREADS, 2)
void sdpa_flash_kernel(const float* __restrict__ q,
                       const float* __restrict__ k,
                       const float* __restrict__ v,
                       const int* __restrict__ km,
                       const int* __restrict__ qm,
                       float* __restrict__ out,
                       float* __restrict__ attn)
{
    extern __shared__ char sm[];
    const uint32_t sbase = s2u(sm);
    float* Qs  = (float*)(sm + OFF_QS);
    float* Zsm = (float*)(sm + OFF_Z);

    const int t = threadIdx.x;
    const int w = t >> 5, l = t & 31;
    const int g = l >> 2, tq = l & 3;
    const int b = blockIdx.y;
    const int q0 = blockIdx.x * TQ;

    const float* kb = k + (size_t)b * LK * DD;
    const float* vb = v + (size_t)b * LK * DD;

    if (t < 32) Zsm[t] = 0.0f;

    // ---- stage Q (fp32) + K chunk 0 (hi/lo fp16) ----
    {
        const float4* qg = (const float4*)(q + ((size_t)b * LQ + q0) * DD);
#pragma unroll
        for (int i = 0; i < 2; i++) {
            int idx = t + NTHREADS * i;
            float4 val = qg[idx];
            *(float4*)&Qs[(idx >> 4) * QSP + ((idx & 15) << 2)] = val;
        }
        const float4* kg = (const float4*)kb;
#pragma unroll
        for (int i = 0; i < 4; i++) {
            int idx = t + NTHREADS * i;            // 0..1023
            float4 val = kg[idx];
            int krow = idx >> 4, d0 = (idx & 15) << 2;
            uint2 hi, lo;
            hi.x = pack_hi(val.x, val.y); hi.y = pack_hi(val.z, val.w);
            lo.x = pack_lo(val.x, val.y, hi.x); lo.y = pack_lo(val.z, val.w, hi.y);
            *(uint2*)(sm + OFF_K0 + (krow * KS + d0) * 2) = hi;
            *(uint2*)(sm + OFF_K0 + KHALF + (krow * KS + d0) * 2) = lo;
        }
    }
    __syncthreads();

    // ---- warp roles + Q fragments ----
    const int rg = w & 1, cg = w >> 1;            // 2 row groups x 4 col groups
    const int r0i = rg * 16 + g, r1i = r0i + 8;
    uint32_t ahh[4][4], alo[4][4];
#pragma unroll
    for (int s = 0; s < 4; s++) {
        int k0 = 16 * s + 2 * tq;
        float2 p00 = *(float2*)&Qs[r0i * QSP + k0];
        float2 p01 = *(float2*)&Qs[r0i * QSP + k0 + 8];
        float2 p10 = *(float2*)&Qs[r1i * QSP + k0];
        float2 p11 = *(float2*)&Qs[r1i * QSP + k0 + 8];
        ahh[s][0] = pack_hi(p00.x, p00.y); alo[s][0] = pack_lo(p00.x, p00.y, ahh[s][0]);
        ahh[s][1] = pack_hi(p10.x, p10.y); alo[s][1] = pack_lo(p10.x, p10.y, ahh[s][1]);
        ahh[s][2] = pack_hi(p01.x, p01.y); alo[s][2] = pack_lo(p01.x, p01.y, ahh[s][2]);
        ahh[s][3] = pack_hi(p11.x, p11.y); alo[s][3] = pack_lo(p11.x, p11.y, ahh[s][3]);
    }

    const size_t growBase = (size_t)b * LQ + q0;
    const size_t mrow0 = (growBase + r0i) * LK + cg * 16 + 2 * tq;
    const size_t mrow1 = mrow0 + 8 * (size_t)LK;

    // masks for chunk 0
    int2 kmc[2][2], qmc[2][2];
#pragma unroll
    for (int nt = 0; nt < 2; nt++) {
        kmc[0][nt] = *(const int2*)(km + mrow0 + nt * 8);
        kmc[1][nt] = *(const int2*)(km + mrow1 + nt * 8);
        qmc[0][nt] = *(const int2*)(qm + mrow0 + nt * 8);
        qmc[1][nt] = *(const int2*)(qm + mrow1 + nt * 8);
    }

    float Z0 = 0.0f, Z1 = 0.0f;
    // generic pointers for E stores (sm-based, NOT sbase-based)
    char* ph_r0 = sm + OFF_PH + r0i * (PHS * 2) + (cg * 16 + 2 * tq) * 2;
    char* ph_r1 = ph_r0 + 8 * (PHS * 2);

    // =================== Phase 1: E = exp(mask(Q K^T / 8)) ===================
    for (int c = 0; c < NCH; c++) {
        float4 kpre[4];
        int2 kmn[2][2], qmn[2][2];
        if (c + 1 < NCH) {
            const float4* kg2 = (const float4*)(kb + (size_t)(c + 1) * TK * DD);
#pragma unroll
            for (int i = 0; i < 4; i++) kpre[i] = kg2[t + NTHREADS * i];
            int off = (c + 1) * TK;
#pragma unroll
            for (int nt = 0; nt < 2; nt++) {
                kmn[0][nt] = *(const int2*)(km + mrow0 + off + nt * 8);
                kmn[1][nt] = *(const int2*)(km + mrow1 + off + nt * 8);
                qmn[0][nt] = *(const int2*)(qm + mrow0 + off + nt * 8);
                qmn[1][nt] = *(const int2*)(qm + mrow1 + off + nt * 8);
            }
        }
        const char* kbuf = sm + ((c & 1) ? OFF_K1 : OFF_K0);

        float acc[2][4];
#pragma unroll
        for (int nt = 0; nt < 2; nt++)
#pragma unroll
            for (int j = 0; j < 4; j++) acc[nt][j] = 0.0f;

#pragma unroll
        for (int s = 0; s < 4; s++) {
#pragma unroll
            for (int nt = 0; nt < 2; nt++) {
                int row = cg * 16 + nt * 8 + g;
                int byte = (row * KS + 16 * s + 2 * tq) * 2;
                uint32_t bh0 = *(const uint32_t*)(kbuf + byte);
                uint32_t bh1 = *(const uint32_t*)(kbuf + byte + 16);
                uint32_t bl0 = *(const uint32_t*)(kbuf + KHALF + byte);
                uint32_t bl1 = *(const uint32_t*)(kbuf + KHALF + byte + 16);
                mma16816(acc[nt][0], acc[nt][1], acc[nt][2], acc[nt][3],
                         ahh[s][0], ahh[s][1], ahh[s][2], ahh[s][3], bh0, bh1);
                mma16816(acc[nt][0], acc[nt][1], acc[nt][2], acc[nt][3],
                         ahh[s][0], ahh[s][1], ahh[s][2], ahh[s][3], bl0, bl1);
                mma16816(acc[nt][0], acc[nt][1], acc[nt][2], acc[nt][3],
                         alo[s][0], alo[s][1], alo[s][2], alo[s][3], bh0, bh1);
            }
        }

        // mask + exp + Z accumulate + fp16 E store
#pragma unroll
        for (int nt = 0; nt < 2; nt++) {
            float e00 = kmc[0][nt].x ? 0.0f : __expf(acc[nt][0] * 0.125f);
            float e01 = kmc[0][nt].y ? 0.0f : __expf(acc[nt][1] * 0.125f);
            float e10 = kmc[1][nt].x ? 0.0f : __expf(acc[nt][2] * 0.125f);
            float e11 = kmc[1][nt].y ? 0.0f : __expf(acc[nt][3] * 0.125f);
            Z0 += e00 + e01;
            Z1 += e10 + e11;
            float s00 = qmc[0][nt].x ? 0.0f : e00;
            float s01 = qmc[0][nt].y ? 0.0f : e01;
            float s10 = qmc[1][nt].x ? 0.0f : e10;
            float s11 = qmc[1][nt].y ? 0.0f : e11;
            int cofs = (c * 64 + nt * 8) * 2;
            *(uint32_t*)(ph_r0 + cofs) = pack_hi(s00, s01);
            *(uint32_t*)(ph_r1 + cofs) = pack_hi(s10, s11);
        }

        if (c + 1 < NCH) {
            char* nbuf = sm + (((c + 1) & 1) ? OFF_K1 : OFF_K0);
#pragma unroll
            for (int i = 0; i < 4; i++) {
                int idx = t + NTHREADS * i;
                int krow = idx >> 4, d0 = (idx & 15) << 2;
                uint2 hi, lo;
                hi.x = pack_hi(kpre[i].x, kpre[i].y); hi.y = pack_hi(kpre[i].z, kpre[i].w);
                lo.x = pack_lo(kpre[i].x, kpre[i].y, hi.x); lo.y = pack_lo(kpre[i].z, kpre[i].w, hi.y);
                *(uint2*)(nbuf + (krow * KS + d0) * 2) = hi;
                *(uint2*)(nbuf + KHALF + (krow * KS + d0) * 2) = lo;
            }
#pragma unroll
            for (int nt = 0; nt < 2; nt++) {
                kmc[0][nt] = kmn[0][nt]; kmc[1][nt] = kmn[1][nt];
                qmc[0][nt] = qmn[0][nt]; qmc[1][nt] = qmn[1][nt];
            }
        }
        __syncthreads();
    }

    // ---- Z reduction: shfl over tq, then smem atomics ----
    Z0 += __shfl_xor_sync(0xffffffffu, Z0, 1);
    Z0 += __shfl_xor_sync(0xffffffffu, Z0, 2);
    Z1 += __shfl_xor_sync(0xffffffffu, Z1, 1);
    Z1 += __shfl_xor_sync(0xffffffffu, Z1, 2);
    if (tq == 0) {
        atomicAdd(&Zsm[r0i], Z0);
        atomicAdd(&Zsm[r1i], Z1);
    }
    __syncthreads();
    if (t < 32) Zsm[t] = 1.0f / Zsm[t];
    __syncthreads();

    // ---- stage V chunk 0 (fp16) into aliased K region ----
    {
        const float4* vg = (const float4*)vb;
#pragma unroll
        for (int i = 0; i < 4; i++) {
            int idx = t + NTHREADS * i;
            float4 val = vg[idx];
            int krow = idx >> 4, d0 = (idx & 15) << 2;
            uint2 h;
            h.x = pack_hi(val.x, val.y); h.y = pack_hi(val.z, val.w);
            *(uint2*)(sm + OFF_V0 + (krow * KS + d0) * 2) = h;
        }
    }

    // ---- attn = E * invZ, fp32 coalesced write ----
    if (attn) {
#pragma unroll
        for (int rr = 0; rr < 4; rr++) {
            const int r = w + (rr << 3);
            const float invZ = Zsm[r];
            float* arow = attn + (growBase + r) * LK;
#pragma unroll
            for (int j = 0; j < 4; j++) {
                int col = 4 * l + 128 * j;
                uint2 hh = *(const uint2*)(sm + OFF_PH + r * (PHS * 2) + col * 2);
                float2 f0 = __half22float2(*(__half2*)&hh.x);
                float2 f1 = __half22float2(*(__half2*)&hh.y);
                *(float4*)(arow + col) = make_float4(f0.x * invZ, f0.y * invZ,
                                                     f1.x * invZ, f1.y * invZ);
            }
        }
    }
    __syncthreads();

    // =================== Phase 2: O = (E V) * invZ ===================
    const int rg2 = w & 1, cg2 = w >> 1;
    float o[2][4];
#pragma unroll
    for (int nt = 0; nt < 2; nt++)
#pragma unroll
        for (int j = 0; j < 4; j++) o[nt][j] = 0.0f;

    const uint32_t a_base = sbase + OFF_PH + (rg2 * 16 + (l & 15)) * (PHS * 2) + ((l >> 4) & 1) * 16;
    const uint32_t b_coloff = (cg2 * 16 + ((l >> 4) & 1) * 8) * 2;

    for (int c = 0; c < NCH; c++) {
        float4 vpre[4];
        if (c + 1 < NCH) {
            const float4* vg2 = (const float4*)(vb + (size_t)(c + 1) * TK * DD);
#pragma unroll
            for (int i = 0; i < 4; i++) vpre[i] = vg2[t + NTHREADS * i];
        }
        const uint32_t vbuf = sbase + ((c & 1) ? OFF_V1 : OFF_V0);
#pragma unroll
        for (int s = 0; s < 4; s++) {
            uint32_t a0, a1, a2, a3, b0, b1, b2, b3;
            ldsm4(a0, a1, a2, a3, a_base + (c * 64 + s * 16) * 2);
            ldsm4t(b0, b1, b2, b3, vbuf + (s * 16 + (l & 15)) * (KS * 2) + b_coloff);
            mma16816(o[0][0], o[0][1], o[0][2], o[0][3], a0, a1, a2, a3, b0, b1);
            mma16816(o[1][0], o[1][1], o[1][2], o[1][3], a0, a1, a2, a3, b2, b3);
        }
        if (c + 1 < NCH) {
            char* nbuf = sm + (((c + 1) & 1) ? OFF_V1 : OFF_V0);
#pragma unroll
            for (int i = 0; i < 4; i++) {
                int idx = t + NTHREADS * i;
                int krow = idx >> 4, d0 = (idx & 15) << 2;
                uint2 h;
                h.x = pack_hi(vpre[i].x, vpre[i].y); h.y = pack_hi(vpre[i].z, vpre[i].w);
                *(uint2*)(nbuf + (krow * KS + d0) * 2) = h;
            }
        }
        __syncthreads();
    }

    // write O with per-row 1/Z
    {
        const int row0 = rg2 * 16 + g;
        const float invZa = Zsm[row0], invZb = Zsm[row0 + 8];
#pragma unroll
        for (int nt = 0; nt < 2; nt++) {
            int col = cg2 * 16 + nt * 8 + 2 * tq;
            *(float2*)(out + (growBase + row0) * DD + col) =
                make_float2(o[nt][0] * invZa, o[nt][1] * invZa);
            *(float2*)(out + (growBase + row0 + 8) * DD + col) =
                make_float2(o[nt][2] * invZb, o[nt][3] * invZb);
        }
    }
}

extern "C" void kernel_launch(void* const* d_in, const int* in_sizes, int n_in,
                              void* d_out, int out_size)
{
    const float* q = (const float*)d_in[0];
    const float* k = (const float*)d_in[1];
    const float* v = (const float*)d_in[2];
    const int* km = (const int*)d_in[3];
    const int* qm = (const int*)d_in[4];

    const long long OUT_N  = (long long)BB * LQ * DD;
    const long long ATTN_N = (long long)BB * LQ * LK;

    float* out_p;
    float* attn_p;
    long long osz = (long long)out_size;
    if (osz >= OUT_N + ATTN_N) {
        out_p  = (float*)d_out;
        attn_p = (float*)d_out + OUT_N;
    } else if (osz == ATTN_N) {
        float* scratch;
        cudaGetSymbolAddress((void**)&scratch, g_out_scratch);
        out_p  = scratch;
        attn_p = (float*)d_out;
    } else {
        out_p  = (float*)d_out;
        attn_p = nullptr;
    }

    cudaFuncSetAttribute(sdpa_flash_kernel, cudaFuncAttributeMaxDynamicSharedMemorySize, SMEM_BYTES);
    dim3 grid(LQ / TQ, BB);
    sdpa_flash_kernel<<<grid, NTHREADS, SMEM_BYTES>>>(q, k, v, km, qm, out_p, attn_p);
}

// round 12
// speedup vs baseline: 4.2074x; 1.0262x over previous
#include <cuda_runtime.h>
#include <cuda_fp16.h>
#include <cfloat>
#include <cstdint>

#define BB 128
#define LQ 512
#define LK 512
#define DD 64
#define TQ 32
#define TK 64
#define NCH (LK/TK)          // 8
#define PHS  520             // fp16 E stride (halves) -> 1040 B/row
#define KS   72              // K/V fp16 row stride (halves) -> 144 B/row
#define QSP  68              // Q fp32 stride
#define NTHREADS 256

// smem byte offsets
#define OFF_PH 0                           // 32*520*2 = 33280
#define OFF_K0 33280                       // hi(9216)+lo(9216)
#define KHALF  9216
#define OFF_K1 (OFF_K0 + 2*KHALF)          // 51712
#define OFF_QS (OFF_K1 + 2*KHALF)          // 70144, 32*68*4 = 8704
#define OFF_Z  (OFF_QS + 8704)             // 78848, 128 B
#define SMEM_BYTES (OFF_Z + 128)           // 78976
#define OFF_V0 OFF_K0                      // V buffers alias K region (fp16 only)
#define OFF_V1 (OFF_K0 + KHALF)

__device__ float g_out_scratch[(size_t)BB * LQ * DD];

static __device__ __forceinline__ uint32_t s2u(const void* p) {
    uint32_t a;
    asm("{ .reg .u64 t; cvta.to.shared.u64 t, %1; cvt.u32.u64 %0, t; }" : "=r"(a) : "l"(p));
    return a;
}
static __device__ __forceinline__ uint32_t pack_hi(float x, float y) {
    __half2 h = __floats2half2_rn(x, y);
    return *(uint32_t*)&h;
}
static __device__ __forceinline__ uint32_t pack_lo(float x, float y, uint32_t hibits) {
    __half2 h = *(__half2*)&hibits;
    float2 hf = __half22float2(h);
    __half2 l = __floats2half2_rn(x - hf.x, y - hf.y);
    return *(uint32_t*)&l;
}
static __device__ __forceinline__ void mma16816(float& c0, float& c1, float& c2, float& c3,
                                                uint32_t a0, uint32_t a1, uint32_t a2, uint32_t a3,
                                                uint32_t b0, uint32_t b1) {
    asm volatile("mma.sync.aligned.m16n8k16.row.col.f32.f16.f16.f32 "
                 "{%0,%1,%2,%3}, {%4,%5,%6,%7}, {%8,%9}, {%0,%1,%2,%3};"
                 : "+f"(c0), "+f"(c1), "+f"(c2), "+f"(c3)
                 : "r"(a0), "r"(a1), "r"(a2), "r"(a3), "r"(b0), "r"(b1));
}
static __device__ __forceinline__ void ldsm4(uint32_t& r0, uint32_t& r1, uint32_t& r2, uint32_t& r3,
                                             uint32_t addr) {
    asm volatile("ldmatrix.sync.aligned.m8n8.x4.shared.b16 {%0,%1,%2,%3}, [%4];"
                 : "=r"(r0), "=r"(r1), "=r"(r2), "=r"(r3) : "r"(addr));
}
static __device__ __forceinline__ void ldsm4t(uint32_t& r0, uint32_t& r1, uint32_t& r2, uint32_t& r3,
                                              uint32_t addr) {
    asm volatile("ldmatrix.sync.aligned.m8n8.x4.trans.shared.b16 {%0,%1,%2,%3}, [%4];"
                 : "=r"(r0), "=r"(r1), "=r"(r2), "=r"(r3) : "r"(addr));
}
// pack 8 mask ints (two rows x 2 nt x 2 cols) into one bitmask
static __device__ __forceinline__ uint32_t pack_mask8(const int* p, size_t r0, size_t r1, int off) {
    int2 a = *(const int2*)(p + r0 + off);
    int2 b = *(const int2*)(p + r0 + off + 8);
    int2 c = *(const int2*)(p + r1 + off);
    int2 d = *(const int2*)(p + r1 + off + 8);
    return (a.x ? 1u : 0u) | (a.y ? 2u : 0u) | (b.x ? 4u : 0u) | (b.y ? 8u : 0u)
         | (c.x ? 16u : 0u) | (c.y ? 32u : 0u) | (d.x ? 64u : 0u) | (d.y ? 128u : 0u);
}

__global__ __launch_bounds__(NTHREADS, 2)
void sdpa_flash_kernel(const float* __restrict__ q,
                       const float* __restrict__ k,
                       const float* __restrict__ v,
                       const int* __restrict__ km,
                       const int* __restrict__ qm,
                       float* __restrict__ out,
                       float* __restrict__ attn)
{
    extern __shared__ char sm[];
    const uint32_t sbase = s2u(sm);
    float* Qs  = (float*)(sm + OFF_QS);
    float* Zsm = (float*)(sm + OFF_Z);

    const int t = threadIdx.x;
    const int w = t >> 5, l = t & 31;
    const int g = l >> 2, tq = l & 3;
    const int b = blockIdx.y;
    const int q0 = blockIdx.x * TQ;

    const float* kb = k + (size_t)b * LK * DD;
    const float* vb = v + (size_t)b * LK * DD;

    if (t < 32) Zsm[t] = 0.0f;

    // ---- stage Q (fp32) + K chunk 0 (hi/lo fp16) ----
    {
        const float4* qg = (const float4*)(q + ((size_t)b * LQ + q0) * DD);
#pragma unroll
        for (int i = 0; i < 2; i++) {
            int idx = t + NTHREADS * i;
            float4 val = qg[idx];
            *(float4*)&Qs[(idx >> 4) * QSP + ((idx & 15) << 2)] = val;
        }
        const float4* kg = (const float4*)kb;
#pragma unroll
        for (int i = 0; i < 4; i++) {
            int idx = t + NTHREADS * i;            // 0..1023
            float4 val = kg[idx];
            int krow = idx >> 4, d0 = (idx & 15) << 2;
            uint2 hi, lo;
            hi.x = pack_hi(val.x, val.y); hi.y = pack_hi(val.z, val.w);
            lo.x = pack_lo(val.x, val.y, hi.x); lo.y = pack_lo(val.z, val.w, hi.y);
            *(uint2*)(sm + OFF_K0 + (krow * KS + d0) * 2) = hi;
            *(uint2*)(sm + OFF_K0 + KHALF + (krow * KS + d0) * 2) = lo;
        }
    }
    __syncthreads();

    // ---- warp roles + Q fragments ----
    const int rg = w & 1, cg = w >> 1;            // 2 row groups x 4 col groups
    const int r0i = rg * 16 + g, r1i = r0i + 8;
    uint32_t ahh[4][4], alo[4][4];
#pragma unroll
    for (int s = 0; s < 4; s++) {
        int k0 = 16 * s + 2 * tq;
        float2 p00 = *(float2*)&Qs[r0i * QSP + k0];
        float2 p01 = *(float2*)&Qs[r0i * QSP + k0 + 8];
        float2 p10 = *(float2*)&Qs[r1i * QSP + k0];
        float2 p11 = *(float2*)&Qs[r1i * QSP + k0 + 8];
        ahh[s][0] = pack_hi(p00.x, p00.y); alo[s][0] = pack_lo(p00.x, p00.y, ahh[s][0]);
        ahh[s][1] = pack_hi(p10.x, p10.y); alo[s][1] = pack_lo(p10.x, p10.y, ahh[s][1]);
        ahh[s][2] = pack_hi(p01.x, p01.y); alo[s][2] = pack_lo(p01.x, p01.y, ahh[s][2]);
        ahh[s][3] = pack_hi(p11.x, p11.y); alo[s][3] = pack_lo(p11.x, p11.y, ahh[s][3]);
    }

    const size_t growBase = (size_t)b * LQ + q0;
    const size_t mrow0 = (growBase + r0i) * LK + cg * 16 + 2 * tq;
    const size_t mrow1 = mrow0 + 8 * (size_t)LK;

    // masks for chunk 0 (packed bitmask: row0 nt0.xy, nt1.xy = bits0-3; row1 = bits4-7)
    uint32_t kmb = pack_mask8(km, mrow0, mrow1, 0);
    uint32_t qmb = pack_mask8(qm, mrow0, mrow1, 0);

    float Z0 = 0.0f, Z1 = 0.0f;
    // generic pointers for E stores (sm-based, NOT sbase-based)
    char* ph_r0 = sm + OFF_PH + r0i * (PHS * 2) + (cg * 16 + 2 * tq) * 2;
    char* ph_r1 = ph_r0 + 8 * (PHS * 2);

    // =================== Phase 1: E = exp(mask(Q K^T / 8)) ===================
    for (int c = 0; c < NCH; c++) {
        float4 kpre[4];
        uint32_t kmn = 0, qmn = 0;
        if (c + 1 < NCH) {
            const float4* kg2 = (const float4*)(kb + (size_t)(c + 1) * TK * DD);
#pragma unroll
            for (int i = 0; i < 4; i++) kpre[i] = kg2[t + NTHREADS * i];
            int off = (c + 1) * TK;
            kmn = pack_mask8(km, mrow0, mrow1, off);
            qmn = pack_mask8(qm, mrow0, mrow1, off);
        }
        const char* kbuf = sm + ((c & 1) ? OFF_K1 : OFF_K0);

        // three independent accumulator chains per nt (hh, hl, lh)
        float ac0[2][4], ac1[2][4], ac2[2][4];
#pragma unroll
        for (int nt = 0; nt < 2; nt++)
#pragma unroll
            for (int j = 0; j < 4; j++) { ac0[nt][j] = 0.0f; ac1[nt][j] = 0.0f; ac2[nt][j] = 0.0f; }

#pragma unroll
        for (int s = 0; s < 4; s++) {
#pragma unroll
            for (int nt = 0; nt < 2; nt++) {
                int row = cg * 16 + nt * 8 + g;
                int byte = (row * KS + 16 * s + 2 * tq) * 2;
                uint32_t bh0 = *(const uint32_t*)(kbuf + byte);
                uint32_t bh1 = *(const uint32_t*)(kbuf + byte + 16);
                uint32_t bl0 = *(const uint32_t*)(kbuf + KHALF + byte);
                uint32_t bl1 = *(const uint32_t*)(kbuf + KHALF + byte + 16);
                mma16816(ac0[nt][0], ac0[nt][1], ac0[nt][2], ac0[nt][3],
                         ahh[s][0], ahh[s][1], ahh[s][2], ahh[s][3], bh0, bh1);
                mma16816(ac1[nt][0], ac1[nt][1], ac1[nt][2], ac1[nt][3],
                         ahh[s][0], ahh[s][1], ahh[s][2], ahh[s][3], bl0, bl1);
                mma16816(ac2[nt][0], ac2[nt][1], ac2[nt][2], ac2[nt][3],
                         alo[s][0], alo[s][1], alo[s][2], alo[s][3], bh0, bh1);
            }
        }

        // mask + exp + Z accumulate + fp16 E store
#pragma unroll
        for (int nt = 0; nt < 2; nt++) {
            float a0 = ac0[nt][0] + ac1[nt][0] + ac2[nt][0];
            float a1 = ac0[nt][1] + ac1[nt][1] + ac2[nt][1];
            float a2 = ac0[nt][2] + ac1[nt][2] + ac2[nt][2];
            float a3 = ac0[nt][3] + ac1[nt][3] + ac2[nt][3];
            float e00 = (kmb & (1u << (2 * nt)))     ? 0.0f : __expf(a0 * 0.125f);
            float e01 = (kmb & (2u << (2 * nt)))     ? 0.0f : __expf(a1 * 0.125f);
            float e10 = (kmb & (16u << (2 * nt)))    ? 0.0f : __expf(a2 * 0.125f);
            float e11 = (kmb & (32u << (2 * nt)))    ? 0.0f : __expf(a3 * 0.125f);
            Z0 += e00 + e01;
            Z1 += e10 + e11;
            float s00 = (qmb & (1u << (2 * nt)))  ? 0.0f : e00;
            float s01 = (qmb & (2u << (2 * nt)))  ? 0.0f : e01;
            float s10 = (qmb & (16u << (2 * nt))) ? 0.0f : e10;
            float s11 = (qmb & (32u << (2 * nt))) ? 0.0f : e11;
            int cofs = (c * 64 + nt * 8) * 2;
            *(uint32_t*)(ph_r0 + cofs) = pack_hi(s00, s01);
            *(uint32_t*)(ph_r1 + cofs) = pack_hi(s10, s11);
        }

        if (c + 1 < NCH) {
            char* nbuf = sm + (((c + 1) & 1) ? OFF_K1 : OFF_K0);
#pragma unroll
            for (int i = 0; i < 4; i++) {
                int idx = t + NTHREADS * i;
                int krow = idx >> 4, d0 = (idx & 15) << 2;
                uint2 hi, lo;
                hi.x = pack_hi(kpre[i].x, kpre[i].y); hi.y = pack_hi(kpre[i].z, kpre[i].w);
                lo.x = pack_lo(kpre[i].x, kpre[i].y, hi.x); lo.y = pack_lo(kpre[i].z, kpre[i].w, hi.y);
                *(uint2*)(nbuf + (krow * KS + d0) * 2) = hi;
                *(uint2*)(nbuf + KHALF + (krow * KS + d0) * 2) = lo;
            }
            kmb = kmn; qmb = qmn;
        }
        __syncthreads();
    }

    // ---- Z reduction: shfl over tq, then smem atomics ----
    Z0 += __shfl_xor_sync(0xffffffffu, Z0, 1);
    Z0 += __shfl_xor_sync(0xffffffffu, Z0, 2);
    Z1 += __shfl_xor_sync(0xffffffffu, Z1, 1);
    Z1 += __shfl_xor_sync(0xffffffffu, Z1, 2);
    if (tq == 0) {
        atomicAdd(&Zsm[r0i], Z0);
        atomicAdd(&Zsm[r1i], Z1);
    }
    __syncthreads();
    if (t < 32) Zsm[t] = 1.0f / Zsm[t];
    __syncthreads();

    // ---- stage V chunk 0 (fp16) into aliased K region ----
    {
        const float4* vg = (const float4*)vb;
#pragma unroll
        for (int i = 0; i < 4; i++) {
            int idx = t + NTHREADS * i;
            float4 val = vg[idx];
            int krow = idx >> 4, d0 = (idx & 15) << 2;
            uint2 h;
            h.x = pack_hi(val.x, val.y); h.y = pack_hi(val.z, val.w);
            *(uint2*)(sm + OFF_V0 + (krow * KS + d0) * 2) = h;
        }
    }

    // ---- attn = E * invZ, fp32 coalesced write ----
    if (attn) {
#pragma unroll
        for (int rr = 0; rr < 4; rr++) {
            const int r = w + (rr << 3);
            const float invZ = Zsm[r];
            float* arow = attn + (growBase + r) * LK;
#pragma unroll
            for (int j = 0; j < 4; j++) {
                int col = 4 * l + 128 * j;
                uint2 hh = *(const uint2*)(sm + OFF_PH + r * (PHS * 2) + col * 2);
                float2 f0 = __half22float2(*(__half2*)&hh.x);
                float2 f1 = __half22float2(*(__half2*)&hh.y);
                *(float4*)(arow + col) = make_float4(f0.x * invZ, f0.y * invZ,
                                                     f1.x * invZ, f1.y * invZ);
            }
        }
    }
    __syncthreads();

    // =================== Phase 2: O = (E V) * invZ ===================
    const int rg2 = w & 1, cg2 = w >> 1;
    float oe[2][4], oo[2][4];
#pragma unroll
    for (int nt = 0; nt < 2; nt++)
#pragma unroll
        for (int j = 0; j < 4; j++) { oe[nt][j] = 0.0f; oo[nt][j] = 0.0f; }

    const uint32_t a_base = sbase + OFF_PH + (rg2 * 16 + (l & 15)) * (PHS * 2) + ((l >> 4) & 1) * 16;
    const uint32_t b_coloff = (cg2 * 16 + ((l >> 4) & 1) * 8) * 2;

    for (int c = 0; c < NCH; c++) {
        float4 vpre[4];
        if (c + 1 < NCH) {
            const float4* vg2 = (const float4*)(vb + (size_t)(c + 1) * TK * DD);
#pragma unroll
            for (int i = 0; i < 4; i++) vpre[i] = vg2[t + NTHREADS * i];
        }
        const uint32_t vbuf = sbase + ((c & 1) ? OFF_V1 : OFF_V0);
#pragma unroll
        for (int s = 0; s < 4; s++) {
            uint32_t a0, a1, a2, a3, b0, b1, b2, b3;
            ldsm4(a0, a1, a2, a3, a_base + (c * 64 + s * 16) * 2);
            ldsm4t(b0, b1, b2, b3, vbuf + (s * 16 + (l & 15)) * (KS * 2) + b_coloff);
            if (s & 1) {
                mma16816(oo[0][0], oo[0][1], oo[0][2], oo[0][3], a0, a1, a2, a3, b0, b1);
                mma16816(oo[1][0], oo[1][1], oo[1][2], oo[1][3], a0, a1, a2, a3, b2, b3);
            } else {
                mma16816(oe[0][0], oe[0][1], oe[0][2], oe[0][3], a0, a1, a2, a3, b0, b1);
                mma16816(oe[1][0], oe[1][1], oe[1][2], oe[1][3], a0, a1, a2, a3, b2, b3);
            }
        }
        if (c + 1 < NCH) {
            char* nbuf = sm + (((c + 1) & 1) ? OFF_V1 : OFF_V0);
#pragma unroll
            for (int i = 0; i < 4; i++) {
                int idx = t + NTHREADS * i;
                int krow = idx >> 4, d0 = (idx & 15) << 2;
                uint2 h;
                h.x = pack_hi(vpre[i].x, vpre[i].y); h.y = pack_hi(vpre[i].z, vpre[i].w);
                *(uint2*)(nbuf + (krow * KS + d0) * 2) = h;
            }
        }
        __syncthreads();
    }

    // write O with per-row 1/Z
    {
        const int row0 = rg2 * 16 + g;
        const float invZa = Zsm[row0], invZb = Zsm[row0 + 8];
#pragma unroll
        for (int nt = 0; nt < 2; nt++) {
            int col = cg2 * 16 + nt * 8 + 2 * tq;
            *(float2*)(out + (growBase + row0) * DD + col) =
                make_float2((oe[nt][0] + oo[nt][0]) * invZa, (oe[nt][1] + oo[nt][1]) * invZa);
            *(float2*)(out + (growBase + row0 + 8) * DD + col) =
                make_float2((oe[nt][2] + oo[nt][2]) * invZb, (oe[nt][3] + oo[nt][3]) * invZb);
        }
    }
}

extern "C" void kernel_launch(void* const* d_in, const int* in_sizes, int n_in,
                              void* d_out, int out_size)
{
    const float* q = (const float*)d_in[0];
    const float* k = (const float*)d_in[1];
    const float* v = (const float*)d_in[2];
    const int* km = (const int*)d_in[3];
    const int* qm = (const int*)d_in[4];

    const long long OUT_N  = (long long)BB * LQ * DD;
    const long long ATTN_N = (long long)BB * LQ * LK;

    float* out_p;
    float* attn_p;
    long long osz = (long long)out_size;
    if (osz >= OUT_N + ATTN_N) {
        out_p  = (float*)d_out;
        attn_p = (float*)d_out + OUT_N;
    } else if (osz == ATTN_N) {
        float* scratch;
        cudaGetSymbolAddress((void**)&scratch, g_out_scratch);
        out_p  = scratch;
        attn_p = (float*)d_out;
    } else {
        out_p  = (float*)d_out;
        attn_p = nullptr;
    }

    cudaFuncSetAttribute(sdpa_flash_kernel, cudaFuncAttributeMaxDynamicSharedMemorySize, SMEM_BYTES);
    dim3 grid(LQ / TQ, BB);
    sdpa_flash_kernel<<<grid, NTHREADS, SMEM_BYTES>>>(q, k, v, km, qm, out_p, attn_p);
}